// round 8
// baseline (speedup 1.0000x reference)
#include <cuda_runtime.h>
#include <cuda_fp16.h>
#include <cstdint>

#define NN 256
#define HH 128
#define RR 8

typedef unsigned long long u64;

// packed f16x2 proj outputs: [2048 rows][64 kpairs]; lo half = even k
__device__ uint32_t g_pi_h[2048 * 64];
__device__ uint32_t g_pj_h[2048 * 64];

// fragment-order position of kpair kp within a row (u32 index):
// slot (s = kp>>3, t' = kp&7): t'<4 -> word 8s+2t' (lo), t'>=4 -> word 8s+2(t'-4)+1 (hi)
#define FPOS(kp) ((((kp) >> 3) << 3) + (((kp) & 3) << 1) + (((kp) >> 2) & 1))

// ---------------- helpers ----------------
__device__ __forceinline__ uint32_t hadd2(uint32_t a, uint32_t b) {
    uint32_t d; asm("add.rn.f16x2 %0, %1, %2;" : "=r"(d) : "r"(a), "r"(b)); return d;
}
__device__ __forceinline__ uint32_t hmax2(uint32_t a, uint32_t b) {
    uint32_t d; asm("max.f16x2 %0, %1, %2;" : "=r"(d) : "r"(a), "r"(b)); return d;
}
__device__ __forceinline__ uint32_t pack_f16x2(float lo, float hi) {
    uint32_t d; asm("cvt.rn.f16x2.f32 %0, %1, %2;" : "=r"(d) : "f"(hi), "f"(lo)); return d;
}
__device__ __forceinline__ void mma16816(float* d, uint32_t a0, uint32_t a1,
                                         uint32_t a2, uint32_t a3,
                                         uint32_t b0, uint32_t b1) {
    asm("mma.sync.aligned.m16n8k16.row.col.f32.f16.f16.f32 "
        "{%0,%1,%2,%3}, {%4,%5,%6,%7}, {%8,%9}, {%0,%1,%2,%3};"
        : "+f"(d[0]), "+f"(d[1]), "+f"(d[2]), "+f"(d[3])
        : "r"(a0), "r"(a1), "r"(a2), "r"(a3), "r"(b0), "r"(b1));
}
// sigmoid(x) = 0.5 + 0.5*tanh(0.5*x); hb carries 0.5*b2 folded in
__device__ __forceinline__ float sigm(float x, float hb) {
    float t, a = fmaf(0.5f, x, hb);
    asm("tanh.approx.f32 %0, %1;" : "=f"(t) : "f"(a));
    return fmaf(0.5f, t, 0.5f);
}

// -------------------------------------------------------------------------
// Phase A (HMMA): proj = slots[2048,256] @ W1cat[256,256] (+b1 on pj half).
// CTA tile 32M x 64N, full K=256. grid (4 ct, 64 rt) x 256 thr.
// As: frag-order u64 rows; Ws: u32 [kp][n] stride 72. Split acc chains.
// -------------------------------------------------------------------------
#define A_STR64 68               // u64 stride (136 u32 words)
#define W_STR 72                 // u32 stride
#define PROJ_SMEM (32 * A_STR64 * 8 + 128 * W_STR * 4)

__global__ __launch_bounds__(256) void proj_kernel(
    const float* __restrict__ slots,
    const float* __restrict__ W1,
    const float* __restrict__ b1)
{
    extern __shared__ __align__(16) u64 psm[];
    uint32_t* Asw = (uint32_t*)psm;              // 32 rows x 136 words
    uint32_t* Ws  = (uint32_t*)(psm + 32 * A_STR64);  // 128 kp x 72 words

    const int tid = threadIdx.x;
    const int ct = blockIdx.x, rt = blockIdx.y;
    const int row0 = rt * 32;
    const int which = ct >> 1;            // 0 -> pi, 1 -> pj
    const int hbase = (ct & 1) * 64;

    // stage slots rows [row0, row0+32): f16x2 in fragment order
    {
        const float2* sp = (const float2*)(slots + (size_t)row0 * 256);
        #pragma unroll
        for (int it = 0; it < 16; it++) {
            int e = tid + it * 256;       // 0..4095
            int r = e >> 7, c2 = e & 127;
            float2 v = sp[r * 128 + c2];
            Asw[r * 136 + FPOS(c2)] = pack_f16x2(v.x, v.y);
        }
    }
    // stage W1 half, cols [hbase,hbase+64): u32 {W1[2kp][n], W1[2kp+1][n]} at [kp][n]
    {
        #pragma unroll
        for (int it = 0; it < 16; it++) {
            int e = tid + it * 256;       // 0..4095
            int kp = e >> 5, n2 = e & 31;
            const float* wb = W1 + (size_t)(which * 256 + 2 * kp) * HH + hbase + 2 * n2;
            float2 f0 = *(const float2*)wb;
            float2 f1 = *(const float2*)(wb + HH);
            u64 two = ((u64)pack_f16x2(f0.y, f1.y) << 32) | pack_f16x2(f0.x, f1.x);
            *(u64*)(Ws + kp * W_STR + 2 * n2) = two;
        }
    }
    __syncthreads();

    const int w = tid >> 5, lane = tid & 31;
    const int g = lane >> 2, t = lane & 3;
    const int wm = w & 1, wn = w >> 1;    // warp tile: 16M x 16N

    float ce[2][4] = {{0.f,0.f,0.f,0.f},{0.f,0.f,0.f,0.f}};
    float co[2][4] = {{0.f,0.f,0.f,0.f},{0.f,0.f,0.f,0.f}};
    const uint32_t* Ar0 = Asw + (wm * 16 + g) * 136;
    const uint32_t* Ar8 = Ar0 + 8 * 136;
    const int n0 = wn * 16 + g;

    #pragma unroll
    for (int s = 0; s < 16; s++) {
        u64 av0 = *(const u64*)(Ar0 + 8 * s + 2 * t);   // {a0, a2}
        u64 av8 = *(const u64*)(Ar8 + 8 * s + 2 * t);   // {a1, a3}
        uint32_t a0 = (uint32_t)av0, a2 = (uint32_t)(av0 >> 32);
        uint32_t a1 = (uint32_t)av8, a3 = (uint32_t)(av8 >> 32);
        const uint32_t* B0 = Ws + (8 * s + t) * W_STR;
        const uint32_t* B4 = B0 + 4 * W_STR;
        float* c0 = (s & 1) ? co[0] : ce[0];
        float* c1 = (s & 1) ? co[1] : ce[1];
        mma16816(c0, a0, a1, a2, a3, B0[n0],     B4[n0]);
        mma16816(c1, a0, a1, a2, a3, B0[n0 + 8], B4[n0 + 8]);
    }

    uint32_t* dst = which ? g_pj_h : g_pi_h;
    #pragma unroll
    for (int nt = 0; nt < 2; nt++) {
        float2 bias = make_float2(0.f, 0.f);
        if (which)
            bias = *(const float2*)(b1 + hbase + wn * 16 + nt * 8 + 2 * t);
        float c0 = ce[nt][0] + co[nt][0] + bias.x;
        float c1 = ce[nt][1] + co[nt][1] + bias.y;
        float c2 = ce[nt][2] + co[nt][2] + bias.x;
        float c3 = ce[nt][3] + co[nt][3] + bias.y;
        int cp = (ct & 1) * 32 + wn * 8 + nt * 4 + t;     // global colpair
        int r0 = row0 + wm * 16 + g;
        dst[(size_t)r0 * 64 + cp]       = pack_f16x2(c0, c1);
        dst[(size_t)(r0 + 8) * 64 + cp] = pack_f16x2(c2, c3);
    }
}

// -------------------------------------------------------------------------
// Phase B (HMMA): CTA = (jhalf, itile, b) = 256 CTAs, 8 warps, warp owns one
// 16-j tile. Dual-i inner loop: two independent HMMA chains per warp sharing
// pj/W2 fragments -> 2x ILP at ~same regs. W2 frags smem-resident.
// -------------------------------------------------------------------------
#define P_STR64 36               // u64 stride (72 words)

__global__ __launch_bounds__(256, 2) void pair_mma_kernel(
    const float* __restrict__ W2,
    const float* __restrict__ b2,
    float* __restrict__ out)
{
    __shared__ __align__(16) u64 pj_s[128 * P_STR64];
    __shared__ __align__(16) u64 pi_s[16 * P_STR64];
    __shared__ __align__(16) u64 w2_s[256];      // [s*32 + lane] = {b0, b1}
    uint32_t* pjw = (uint32_t*)pj_s;
    uint32_t* piw = (uint32_t*)pi_s;

    const int tid = threadIdx.x;
    const int w = tid >> 5, lane = tid & 31;
    const int g = lane >> 2, t = lane & 3;
    const int jhalf = blockIdx.x, itile = blockIdx.y, b = blockIdx.z;

    // stage pj/pi in fragment order
    {
        const u64* src = (const u64*)(g_pj_h + (((size_t)b * NN + jhalf * 128) << 6));
        #pragma unroll
        for (int it = 0; it < 16; it++) {
            int e = tid + it * 256;        // 0..4095
            int row = e >> 5, m = e & 31;
            u64 v = src[e];
            pjw[row * 72 + FPOS(2 * m)]     = (uint32_t)v;
            pjw[row * 72 + FPOS(2 * m + 1)] = (uint32_t)(v >> 32);
        }
        const u64* si = (const u64*)(g_pi_h + (((size_t)b * NN + itile * 16) << 6));
        #pragma unroll
        for (int it = 0; it < 2; it++) {
            int e = tid + it * 256;        // 0..511
            int row = e >> 5, m = e & 31;
            u64 v = si[e];
            piw[row * 72 + FPOS(2 * m)]     = (uint32_t)v;
            piw[row * 72 + FPOS(2 * m + 1)] = (uint32_t)(v >> 32);
        }
    }
    // W2 fragment for (s = w, lane): b0 = {W2[k0][g],W2[k0+1][g]}, k0 = 16s+2t
    {
        int k0 = 16 * w + 2 * t;
        uint32_t f0 = pack_f16x2(W2[k0 * RR + g],       W2[(k0 + 1) * RR + g]);
        uint32_t f1 = pack_f16x2(W2[(k0 + 8) * RR + g], W2[(k0 + 9) * RR + g]);
        w2_s[tid] = ((u64)f1 << 32) | f0;
    }
    const float2 b2v = *(const float2*)(b2 + 2 * t);
    const float hbx = 0.5f * b2v.x, hby = 0.5f * b2v.y;

    __syncthreads();

    // hoist pj fragments (reused across all 16 i)
    u64 pjf[8][2];
    {
        const uint32_t* r0 = pjw + (w * 16 + g) * 72;
        const uint32_t* r8 = r0 + 8 * 72;
        #pragma unroll
        for (int s = 0; s < 8; s++) {
            pjf[s][0] = *(const u64*)(r0 + 8 * s + 2 * t);
            pjf[s][1] = *(const u64*)(r8 + 8 * s + 2 * t);
        }
    }

    const size_t obase = (((size_t)b * NN + itile * 16) * NN + jhalf * 128 + w * 16) * RR;

    #pragma unroll 1
    for (int ii = 0; ii < 8; ii++) {
        const uint32_t* pir0 = piw + (2 * ii) * 72 + 2 * t;
        const uint32_t* pir1 = pir0 + 72;
        float d0[4] = {0.f, 0.f, 0.f, 0.f};
        float d1[4] = {0.f, 0.f, 0.f, 0.f};
        #pragma unroll
        for (int s = 0; s < 8; s++) {
            u64 wv = w2_s[s * 32 + lane];
            uint32_t wb0 = (uint32_t)wv, wb1 = (uint32_t)(wv >> 32);
            u64 pj0 = pjf[s][0], pj1 = pjf[s][1];
            uint32_t pj0l = (uint32_t)pj0, pj0h = (uint32_t)(pj0 >> 32);
            uint32_t pj1l = (uint32_t)pj1, pj1h = (uint32_t)(pj1 >> 32);
            u64 p0 = *(const u64*)(pir0 + 8 * s);   // broadcast LDS.64 (i0)
            u64 p1 = *(const u64*)(pir1 + 8 * s);   // broadcast LDS.64 (i1)
            {
                uint32_t lo = (uint32_t)p0, hi = (uint32_t)(p0 >> 32);
                uint32_t a0 = hmax2(hadd2(pj0l, lo), 0u);
                uint32_t a1 = hmax2(hadd2(pj1l, lo), 0u);
                uint32_t a2 = hmax2(hadd2(pj0h, hi), 0u);
                uint32_t a3 = hmax2(hadd2(pj1h, hi), 0u);
                mma16816(d0, a0, a1, a2, a3, wb0, wb1);
            }
            {
                uint32_t lo = (uint32_t)p1, hi = (uint32_t)(p1 >> 32);
                uint32_t a0 = hmax2(hadd2(pj0l, lo), 0u);
                uint32_t a1 = hmax2(hadd2(pj1l, lo), 0u);
                uint32_t a2 = hmax2(hadd2(pj0h, hi), 0u);
                uint32_t a3 = hmax2(hadd2(pj1h, hi), 0u);
                mma16816(d1, a0, a1, a2, a3, wb0, wb1);
            }
        }
        float* op0 = out + obase + (size_t)(2 * ii) * NN * RR + 2 * t;
        float* op1 = op0 + NN * RR;
        *(float2*)(op0 + g * RR)       = make_float2(sigm(d0[0], hbx), sigm(d0[1], hby));
        *(float2*)(op0 + (g + 8) * RR) = make_float2(sigm(d0[2], hbx), sigm(d0[3], hby));
        *(float2*)(op1 + g * RR)       = make_float2(sigm(d1[0], hbx), sigm(d1[1], hby));
        *(float2*)(op1 + (g + 8) * RR) = make_float2(sigm(d1[2], hbx), sigm(d1[3], hby));
    }
}

extern "C" void kernel_launch(void* const* d_in, const int* in_sizes, int n_in,
                              void* d_out, int out_size)
{
    const float* slots = (const float*)d_in[0];
    const float* W1    = (const float*)d_in[1];
    const float* b1    = (const float*)d_in[2];
    const float* W2    = (const float*)d_in[3];
    const float* b2    = (const float*)d_in[4];
    float* out = (float*)d_out;

    cudaFuncSetAttribute(proj_kernel,
                         cudaFuncAttributeMaxDynamicSharedMemorySize, PROJ_SMEM);

    proj_kernel<<<dim3(4, 64), 256, PROJ_SMEM>>>(slots, W1, b1);
    pair_mma_kernel<<<dim3(2, 16, 8), 256>>>(W2, b2, out);
}

// round 9
// speedup vs baseline: 1.0152x; 1.0152x over previous
#include <cuda_runtime.h>
#include <cuda_fp16.h>
#include <cstdint>

#define NN 256
#define HH 128
#define RR 8

typedef unsigned long long u64;

// packed f16x2 proj outputs: [2048 rows][64 kpairs]; lo half = even k
__device__ uint32_t g_pi_h[2048 * 64];
__device__ uint32_t g_pj_h[2048 * 64];

// fragment-order position of kpair kp within a row (u32 index):
// slot (s = kp>>3, t' = kp&7): t'<4 -> word 8s+2t' (lo), t'>=4 -> word 8s+2(t'-4)+1 (hi)
#define FPOS(kp) ((((kp) >> 3) << 3) + (((kp) & 3) << 1) + (((kp) >> 2) & 1))

// ---------------- helpers ----------------
__device__ __forceinline__ uint32_t hadd2(uint32_t a, uint32_t b) {
    uint32_t d; asm("add.rn.f16x2 %0, %1, %2;" : "=r"(d) : "r"(a), "r"(b)); return d;
}
__device__ __forceinline__ uint32_t hmax2(uint32_t a, uint32_t b) {
    uint32_t d; asm("max.f16x2 %0, %1, %2;" : "=r"(d) : "r"(a), "r"(b)); return d;
}
__device__ __forceinline__ uint32_t pack_f16x2(float lo, float hi) {
    uint32_t d; asm("cvt.rn.f16x2.f32 %0, %1, %2;" : "=r"(d) : "f"(hi), "f"(lo)); return d;
}
__device__ __forceinline__ void mma16816(float* d, uint32_t a0, uint32_t a1,
                                         uint32_t a2, uint32_t a3,
                                         uint32_t b0, uint32_t b1) {
    asm("mma.sync.aligned.m16n8k16.row.col.f32.f16.f16.f32 "
        "{%0,%1,%2,%3}, {%4,%5,%6,%7}, {%8,%9}, {%0,%1,%2,%3};"
        : "+f"(d[0]), "+f"(d[1]), "+f"(d[2]), "+f"(d[3])
        : "r"(a0), "r"(a1), "r"(a2), "r"(a3), "r"(b0), "r"(b1));
}
// sigmoid(x) = 0.5 + 0.5*tanh(0.5*x); hb carries 0.5*b2 folded in
__device__ __forceinline__ float sigm(float x, float hb) {
    float t, a = fmaf(0.5f, x, hb);
    asm("tanh.approx.f32 %0, %1;" : "=f"(t) : "f"(a));
    return fmaf(0.5f, t, 0.5f);
}

// -------------------------------------------------------------------------
// Phase A (HMMA): proj = slots[2048,256] @ W1cat[256,256] (+b1 on pj half).
// CTA tile 32M x 64N, full K=256. grid (4 ct, 64 rt) x 256 thr.
// -------------------------------------------------------------------------
#define A_STR64 68               // u64 stride (136 u32 words)
#define W_STR 72                 // u32 stride
#define PROJ_SMEM (32 * A_STR64 * 8 + 128 * W_STR * 4)

__global__ __launch_bounds__(256) void proj_kernel(
    const float* __restrict__ slots,
    const float* __restrict__ W1,
    const float* __restrict__ b1)
{
    extern __shared__ __align__(16) u64 psm[];
    uint32_t* Asw = (uint32_t*)psm;              // 32 rows x 136 words
    uint32_t* Ws  = (uint32_t*)(psm + 32 * A_STR64);  // 128 kp x 72 words

    const int tid = threadIdx.x;
    const int ct = blockIdx.x, rt = blockIdx.y;
    const int row0 = rt * 32;
    const int which = ct >> 1;            // 0 -> pi, 1 -> pj
    const int hbase = (ct & 1) * 64;

    // stage slots rows [row0, row0+32): f16x2 in fragment order
    {
        const float2* sp = (const float2*)(slots + (size_t)row0 * 256);
        #pragma unroll
        for (int it = 0; it < 16; it++) {
            int e = tid + it * 256;       // 0..4095
            int r = e >> 7, c2 = e & 127;
            float2 v = sp[r * 128 + c2];
            Asw[r * 136 + FPOS(c2)] = pack_f16x2(v.x, v.y);
        }
    }
    // stage W1 half, cols [hbase,hbase+64): u32 {W1[2kp][n], W1[2kp+1][n]} at [kp][n]
    {
        #pragma unroll
        for (int it = 0; it < 16; it++) {
            int e = tid + it * 256;       // 0..4095
            int kp = e >> 5, n2 = e & 31;
            const float* wb = W1 + (size_t)(which * 256 + 2 * kp) * HH + hbase + 2 * n2;
            float2 f0 = *(const float2*)wb;
            float2 f1 = *(const float2*)(wb + HH);
            u64 two = ((u64)pack_f16x2(f0.y, f1.y) << 32) | pack_f16x2(f0.x, f1.x);
            *(u64*)(Ws + kp * W_STR + 2 * n2) = two;
        }
    }
    __syncthreads();

    const int w = tid >> 5, lane = tid & 31;
    const int g = lane >> 2, t = lane & 3;
    const int wm = w & 1, wn = w >> 1;    // warp tile: 16M x 16N

    float ce[2][4] = {{0.f,0.f,0.f,0.f},{0.f,0.f,0.f,0.f}};
    float co[2][4] = {{0.f,0.f,0.f,0.f},{0.f,0.f,0.f,0.f}};
    const uint32_t* Ar0 = Asw + (wm * 16 + g) * 136;
    const uint32_t* Ar8 = Ar0 + 8 * 136;
    const int n0 = wn * 16 + g;

    #pragma unroll
    for (int s = 0; s < 16; s++) {
        u64 av0 = *(const u64*)(Ar0 + 8 * s + 2 * t);   // {a0, a2}
        u64 av8 = *(const u64*)(Ar8 + 8 * s + 2 * t);   // {a1, a3}
        uint32_t a0 = (uint32_t)av0, a2 = (uint32_t)(av0 >> 32);
        uint32_t a1 = (uint32_t)av8, a3 = (uint32_t)(av8 >> 32);
        const uint32_t* B0 = Ws + (8 * s + t) * W_STR;
        const uint32_t* B4 = B0 + 4 * W_STR;
        float* c0 = (s & 1) ? co[0] : ce[0];
        float* c1 = (s & 1) ? co[1] : ce[1];
        mma16816(c0, a0, a1, a2, a3, B0[n0],     B4[n0]);
        mma16816(c1, a0, a1, a2, a3, B0[n0 + 8], B4[n0 + 8]);
    }

    uint32_t* dst = which ? g_pj_h : g_pi_h;
    #pragma unroll
    for (int nt = 0; nt < 2; nt++) {
        float2 bias = make_float2(0.f, 0.f);
        if (which)
            bias = *(const float2*)(b1 + hbase + wn * 16 + nt * 8 + 2 * t);
        float c0 = ce[nt][0] + co[nt][0] + bias.x;
        float c1 = ce[nt][1] + co[nt][1] + bias.y;
        float c2 = ce[nt][2] + co[nt][2] + bias.x;
        float c3 = ce[nt][3] + co[nt][3] + bias.y;
        int cp = (ct & 1) * 32 + wn * 8 + nt * 4 + t;     // global colpair
        int r0 = row0 + wm * 16 + g;
        dst[(size_t)r0 * 64 + cp]       = pack_f16x2(c0, c1);
        dst[(size_t)(r0 + 8) * 64 + cp] = pack_f16x2(c2, c3);
    }
}

// -------------------------------------------------------------------------
// Phase B (HMMA): CTA = (jhalf, itile, b) = 256 CTAs, 8 warps, warp owns one
// 16-j tile. Dual-i inner loop (two independent HMMA chains sharing pj/W2
// fragments). W2 + pj fragments hoisted in regs; 3 CTAs/SM for TLP.
// -------------------------------------------------------------------------
#define P_STR64 36               // u64 stride (72 words)

__global__ __launch_bounds__(256, 3) void pair_mma_kernel(
    const float* __restrict__ W2,
    const float* __restrict__ b2,
    float* __restrict__ out)
{
    __shared__ __align__(16) u64 pj_s[128 * P_STR64];
    __shared__ __align__(16) u64 pi_s[16 * P_STR64];
    __shared__ __align__(16) u64 w2_s[256];      // [s*32 + lane] = {b0, b1}
    uint32_t* pjw = (uint32_t*)pj_s;
    uint32_t* piw = (uint32_t*)pi_s;

    const int tid = threadIdx.x;
    const int w = tid >> 5, lane = tid & 31;
    const int g = lane >> 2, t = lane & 3;
    const int jhalf = blockIdx.x, itile = blockIdx.y, b = blockIdx.z;

    // stage pj/pi in fragment order
    {
        const u64* src = (const u64*)(g_pj_h + (((size_t)b * NN + jhalf * 128) << 6));
        #pragma unroll
        for (int it = 0; it < 16; it++) {
            int e = tid + it * 256;        // 0..4095
            int row = e >> 5, m = e & 31;
            u64 v = src[e];
            pjw[row * 72 + FPOS(2 * m)]     = (uint32_t)v;
            pjw[row * 72 + FPOS(2 * m + 1)] = (uint32_t)(v >> 32);
        }
        const u64* si = (const u64*)(g_pi_h + (((size_t)b * NN + itile * 16) << 6));
        #pragma unroll
        for (int it = 0; it < 2; it++) {
            int e = tid + it * 256;        // 0..511
            int row = e >> 5, m = e & 31;
            u64 v = si[e];
            piw[row * 72 + FPOS(2 * m)]     = (uint32_t)v;
            piw[row * 72 + FPOS(2 * m + 1)] = (uint32_t)(v >> 32);
        }
    }
    // W2 fragment for (s = w, lane): b0 = {W2[k0][g],W2[k0+1][g]}, k0 = 16s+2t
    {
        int k0 = 16 * w + 2 * t;
        uint32_t f0 = pack_f16x2(W2[k0 * RR + g],       W2[(k0 + 1) * RR + g]);
        uint32_t f1 = pack_f16x2(W2[(k0 + 8) * RR + g], W2[(k0 + 9) * RR + g]);
        w2_s[tid] = ((u64)f1 << 32) | f0;
    }
    const float2 b2v = *(const float2*)(b2 + 2 * t);
    const float hbx = 0.5f * b2v.x, hby = 0.5f * b2v.y;

    __syncthreads();

    // hoist pj + W2 fragments into regs (reused across all 16 i)
    u64 pjf[8][2];
    u64 w2f[8];
    {
        const uint32_t* r0 = pjw + (w * 16 + g) * 72;
        const uint32_t* r8 = r0 + 8 * 72;
        #pragma unroll
        for (int s = 0; s < 8; s++) {
            pjf[s][0] = *(const u64*)(r0 + 8 * s + 2 * t);
            pjf[s][1] = *(const u64*)(r8 + 8 * s + 2 * t);
            w2f[s] = w2_s[s * 32 + lane];
        }
    }

    const size_t obase = (((size_t)b * NN + itile * 16) * NN + jhalf * 128 + w * 16) * RR;

    #pragma unroll 1
    for (int ii = 0; ii < 8; ii++) {
        const uint32_t* pir0 = piw + (2 * ii) * 72 + 2 * t;
        const uint32_t* pir1 = pir0 + 72;
        float d0[4] = {0.f, 0.f, 0.f, 0.f};
        float d1[4] = {0.f, 0.f, 0.f, 0.f};
        #pragma unroll
        for (int s = 0; s < 8; s++) {
            uint32_t wb0 = (uint32_t)w2f[s], wb1 = (uint32_t)(w2f[s] >> 32);
            u64 pj0 = pjf[s][0], pj1 = pjf[s][1];
            uint32_t pj0l = (uint32_t)pj0, pj0h = (uint32_t)(pj0 >> 32);
            uint32_t pj1l = (uint32_t)pj1, pj1h = (uint32_t)(pj1 >> 32);
            u64 p0 = *(const u64*)(pir0 + 8 * s);   // broadcast LDS.64 (i0)
            u64 p1 = *(const u64*)(pir1 + 8 * s);   // broadcast LDS.64 (i1)
            {
                uint32_t lo = (uint32_t)p0, hi = (uint32_t)(p0 >> 32);
                uint32_t a0 = hmax2(hadd2(pj0l, lo), 0u);
                uint32_t a1 = hmax2(hadd2(pj1l, lo), 0u);
                uint32_t a2 = hmax2(hadd2(pj0h, hi), 0u);
                uint32_t a3 = hmax2(hadd2(pj1h, hi), 0u);
                mma16816(d0, a0, a1, a2, a3, wb0, wb1);
            }
            {
                uint32_t lo = (uint32_t)p1, hi = (uint32_t)(p1 >> 32);
                uint32_t a0 = hmax2(hadd2(pj0l, lo), 0u);
                uint32_t a1 = hmax2(hadd2(pj1l, lo), 0u);
                uint32_t a2 = hmax2(hadd2(pj0h, hi), 0u);
                uint32_t a3 = hmax2(hadd2(pj1h, hi), 0u);
                mma16816(d1, a0, a1, a2, a3, wb0, wb1);
            }
        }
        float* op0 = out + obase + (size_t)(2 * ii) * NN * RR + 2 * t;
        float* op1 = op0 + NN * RR;
        *(float2*)(op0 + g * RR)       = make_float2(sigm(d0[0], hbx), sigm(d0[1], hby));
        *(float2*)(op0 + (g + 8) * RR) = make_float2(sigm(d0[2], hbx), sigm(d0[3], hby));
        *(float2*)(op1 + g * RR)       = make_float2(sigm(d1[0], hbx), sigm(d1[1], hby));
        *(float2*)(op1 + (g + 8) * RR) = make_float2(sigm(d1[2], hbx), sigm(d1[3], hby));
    }
}

extern "C" void kernel_launch(void* const* d_in, const int* in_sizes, int n_in,
                              void* d_out, int out_size)
{
    const float* slots = (const float*)d_in[0];
    const float* W1    = (const float*)d_in[1];
    const float* b1    = (const float*)d_in[2];
    const float* W2    = (const float*)d_in[3];
    const float* b2    = (const float*)d_in[4];
    float* out = (float*)d_out;

    cudaFuncSetAttribute(proj_kernel,
                         cudaFuncAttributeMaxDynamicSharedMemorySize, PROJ_SMEM);

    proj_kernel<<<dim3(4, 64), 256, PROJ_SMEM>>>(slots, W1, b1);
    pair_mma_kernel<<<dim3(2, 16, 8), 256>>>(W2, b2, out);
}